// round 4
// baseline (speedup 1.0000x reference)
#include <cuda_runtime.h>
#include <cuda_fp16.h>
#include <math_constants.h>

#define BATCH 1024
#define NGENE 8192
#define NSETS 2048
#define MAX_TOTAL 262144   // >= 2048 * 120
#define SPB 8              // sets per block in k_agg

// Scratch (static device globals — no runtime allocation)
__device__ __half g_GT[NGENE * BATCH];  // transposed features, fp16, 16.8 MB
__device__ float  g_w[MAX_TOTAL];       // softmax weights per edge
__device__ int    g_off[NSETS + 1];     // segment start offsets

// ---------------------------------------------------------------------------
// K1: segment boundary detection (segment_ids sorted, all segments nonempty)
// ---------------------------------------------------------------------------
__global__ void k_offsets(const int* __restrict__ seg, int total) {
    int p = blockIdx.x * blockDim.x + threadIdx.x;
    if (p >= total) return;
    if (p == 0) g_off[0] = 0;
    else {
        int s = seg[p];
        if (seg[p - 1] != s) g_off[s] = p;
    }
    if (p == total - 1) g_off[NSETS] = total;
}

// ---------------------------------------------------------------------------
// K2: warp-per-segment softmax over attn_logits -> g_w
// ---------------------------------------------------------------------------
__global__ void k_softmax(const float* __restrict__ logits) {
    int warp_id = (blockIdx.x * blockDim.x + threadIdx.x) >> 5;
    if (warp_id >= NSETS) return;
    int lane = threadIdx.x & 31;
    int beg = g_off[warp_id];
    int end = g_off[warp_id + 1];

    float m = -CUDART_INF_F;
    for (int p = beg + lane; p < end; p += 32) m = fmaxf(m, logits[p]);
    #pragma unroll
    for (int o = 16; o; o >>= 1) m = fmaxf(m, __shfl_xor_sync(0xFFFFFFFFu, m, o));

    float sum = 0.0f;
    for (int p = beg + lane; p < end; p += 32) {
        float e = __expf(logits[p] - m);
        g_w[p] = e;
        sum += e;
    }
    #pragma unroll
    for (int o = 16; o; o >>= 1) sum += __shfl_xor_sync(0xFFFFFFFFu, sum, o);

    float inv = (sum > 0.0f) ? (1.0f / sum) : 0.0f;
    for (int p = beg + lane; p < end; p += 32) g_w[p] *= inv;
}

// ---------------------------------------------------------------------------
// K3: tiled transpose + fp16 convert: G(1024 x 8192) f32 -> GT(8192 x 1024) f16
// blockDim (32,8), grid (NGENE/32, BATCH/32)
// ---------------------------------------------------------------------------
__global__ void k_transpose(const float* __restrict__ G) {
    __shared__ float tile[32][33];
    int gx = blockIdx.x * 32;   // gene base
    int by = blockIdx.y * 32;   // batch base
    int x = gx + threadIdx.x;
    #pragma unroll
    for (int j = 0; j < 32; j += 8)
        tile[threadIdx.y + j][threadIdx.x] = G[(by + threadIdx.y + j) * NGENE + x];
    __syncthreads();
    #pragma unroll
    for (int j = 0; j < 32; j += 8)
        g_GT[(gx + threadIdx.y + j) * BATCH + by + threadIdx.x] =
            __float2half_rn(tile[threadIdx.x][threadIdx.y + j]);
}

// ---------------------------------------------------------------------------
// K4: aggregation. Block = (8 consecutive sets) x (512 batch rows).
// grid = (NSETS/SPB) * 2 = 512 blocks, 256 threads.
// Each thread covers 2 adjacent batch rows per edge via one half2 load
// (warp gather = 128B = 1 fully-used wavefront). Per-set accumulators are
// staged in shared, then stored as contiguous 32B chunks out[b, s0..s0+7].
// ---------------------------------------------------------------------------
__global__ __launch_bounds__(256) void k_agg(const int* __restrict__ flat_idx,
                                             float* __restrict__ out) {
    int sg    = blockIdx.x >> 1;      // set group 0..255
    int halfb = blockIdx.x & 1;       // batch half 0..1
    int s0    = sg * SPB;
    int rb    = halfb * 512;          // batch row base
    int t     = threadIdx.x;

    __shared__ int   sh_idx[SPB * 128];
    __shared__ float sh_w  [SPB * 128];
    __shared__ int   sh_n  [SPB];
    __shared__ float sh_out[SPB * 512];   // [set][local batch row]

    // Stage edge lists for the 8 sets
    #pragma unroll
    for (int j = 0; j < SPB; j++) {
        int beg = g_off[s0 + j];
        int n   = g_off[s0 + j + 1] - beg;
        if (n > 128) n = 128;             // structural: n <= 120
        if (t == 0) sh_n[j] = n;
        if (t < n) {
            sh_idx[j * 128 + t] = flat_idx[beg + t];
            sh_w  [j * 128 + t] = g_w[beg + t];
        }
    }
    __syncthreads();

    const unsigned* __restrict__ GT32 = reinterpret_cast<const unsigned*>(g_GT);
    int colbase = (rb >> 1) + t;          // uint (half2) index within a GT row

    for (int j = 0; j < SPB; j++) {
        int n = sh_n[j];
        const int*   ji = sh_idx + j * 128;
        const float* jw = sh_w   + j * 128;
        float2 acc = make_float2(0.f, 0.f);
        #pragma unroll 4
        for (int i = 0; i < n; i++) {
            float    w = jw[i];
            unsigned u = GT32[ji[i] * (BATCH / 2) + colbase];
            float2   v = __half22float2(*reinterpret_cast<const __half2*>(&u));
            acc.x += w * v.x;
            acc.y += w * v.y;
        }
        *reinterpret_cast<float2*>(&sh_out[j * 512 + 2 * t]) = acc;
    }
    __syncthreads();

    // Coalesced stores: thread covers local rows t and t+256, 32B each
    #pragma unroll
    for (int r = 0; r < 2; r++) {
        int lb = t + r * 256;
        int b  = rb + lb;
        float4 v0, v1;
        v0.x = sh_out[0 * 512 + lb]; v0.y = sh_out[1 * 512 + lb];
        v0.z = sh_out[2 * 512 + lb]; v0.w = sh_out[3 * 512 + lb];
        v1.x = sh_out[4 * 512 + lb]; v1.y = sh_out[5 * 512 + lb];
        v1.z = sh_out[6 * 512 + lb]; v1.w = sh_out[7 * 512 + lb];
        float4* o = reinterpret_cast<float4*>(out + (size_t)b * NSETS + s0);
        o[0] = v0;
        o[1] = v1;
    }
}

// ---------------------------------------------------------------------------
// Launcher (graph-capturable: kernel launches only, default stream ordering)
// ---------------------------------------------------------------------------
extern "C" void kernel_launch(void* const* d_in, const int* in_sizes, int n_in,
                              void* d_out, int out_size) {
    const float* G      = (const float*)d_in[0];
    const float* logits = (const float*)d_in[1];
    const int*   fidx   = (const int*)d_in[2];
    const int*   seg    = (const int*)d_in[3];
    float*       out    = (float*)d_out;
    int total = in_sizes[1];

    k_offsets<<<(total + 255) / 256, 256>>>(seg, total);
    k_softmax<<<(NSETS * 32 + 255) / 256, 256>>>(logits);
    k_transpose<<<dim3(NGENE / 32, BATCH / 32), dim3(32, 8)>>>(G);
    k_agg<<<(NSETS / SPB) * 2, 256>>>(fidx, out);
}

// round 5
// speedup vs baseline: 1.4634x; 1.4634x over previous
#include <cuda_runtime.h>
#include <cuda_fp16.h>
#include <math_constants.h>

#define BATCH 1024
#define NGENE 8192
#define NSETS 2048
#define MAX_TOTAL 262144   // >= 2048 * 120

// Scratch (static device globals — no runtime allocation)
__device__ __half g_GT[NGENE * BATCH];    // transposed features, fp16, 16.8 MB
__device__ float  g_outT[NSETS * BATCH];  // set-major output staging, 8.4 MB
__device__ float  g_w[MAX_TOTAL];         // softmax weights per edge
__device__ int    g_off[NSETS + 1];       // segment start offsets

// ---------------------------------------------------------------------------
// K1: segment boundary detection (segment_ids sorted, all segments nonempty)
// ---------------------------------------------------------------------------
__global__ void k_offsets(const int* __restrict__ seg, int total) {
    int p = blockIdx.x * blockDim.x + threadIdx.x;
    if (p >= total) return;
    if (p == 0) g_off[0] = 0;
    else {
        int s = seg[p];
        if (seg[p - 1] != s) g_off[s] = p;
    }
    if (p == total - 1) g_off[NSETS] = total;
}

// ---------------------------------------------------------------------------
// K2: warp-per-segment softmax over attn_logits -> g_w
// ---------------------------------------------------------------------------
__global__ void k_softmax(const float* __restrict__ logits) {
    int warp_id = (blockIdx.x * blockDim.x + threadIdx.x) >> 5;
    if (warp_id >= NSETS) return;
    int lane = threadIdx.x & 31;
    int beg = g_off[warp_id];
    int end = g_off[warp_id + 1];

    float m = -CUDART_INF_F;
    for (int p = beg + lane; p < end; p += 32) m = fmaxf(m, logits[p]);
    #pragma unroll
    for (int o = 16; o; o >>= 1) m = fmaxf(m, __shfl_xor_sync(0xFFFFFFFFu, m, o));

    float sum = 0.0f;
    for (int p = beg + lane; p < end; p += 32) {
        float e = __expf(logits[p] - m);
        g_w[p] = e;
        sum += e;
    }
    #pragma unroll
    for (int o = 16; o; o >>= 1) sum += __shfl_xor_sync(0xFFFFFFFFu, sum, o);

    float inv = (sum > 0.0f) ? (1.0f / sum) : 0.0f;
    for (int p = beg + lane; p < end; p += 32) g_w[p] *= inv;
}

// ---------------------------------------------------------------------------
// K3: tiled transpose + fp16 convert: G(1024 x 8192) f32 -> GT(8192 x 1024) f16
// blockDim (32,8), grid (NGENE/32, BATCH/32)
// ---------------------------------------------------------------------------
__global__ void k_transpose(const float* __restrict__ G) {
    __shared__ float tile[32][33];
    int gx = blockIdx.x * 32;   // gene base
    int by = blockIdx.y * 32;   // batch base
    int x = gx + threadIdx.x;
    #pragma unroll
    for (int j = 0; j < 32; j += 8)
        tile[threadIdx.y + j][threadIdx.x] = G[(by + threadIdx.y + j) * NGENE + x];
    __syncthreads();
    #pragma unroll
    for (int j = 0; j < 32; j += 8)
        g_GT[(gx + threadIdx.y + j) * BATCH + by + threadIdx.x] =
            __float2half_rn(tile[threadIdx.x][threadIdx.y + j]);
}

// ---------------------------------------------------------------------------
// K4: block-per-set aggregation (grid = 2048, 256 threads).
// Thread t owns batch rows 4t..4t+3: one uint2 (4 halfs, 8B) per edge,
// warp gather = 256B = 2 fully-used wavefronts. Stores go set-major into
// g_outT fully coalesced (float4, 32 store wavefronts per block).
// ---------------------------------------------------------------------------
__global__ __launch_bounds__(256) void k_agg(const int* __restrict__ flat_idx) {
    int s = blockIdx.x;
    int beg = g_off[s];
    int n = g_off[s + 1] - beg;
    if (n > 128) n = 128;   // structural: n <= 120

    __shared__ int   sh_idx[128];
    __shared__ float sh_w[128];
    int t = threadIdx.x;
    if (t < n) {
        sh_idx[t] = flat_idx[beg + t];
        sh_w[t]   = g_w[beg + t];
    }
    __syncthreads();

    const uint2* __restrict__ GT64 = reinterpret_cast<const uint2*>(g_GT);
    float4 acc = make_float4(0.f, 0.f, 0.f, 0.f);

    #pragma unroll 8
    for (int i = 0; i < n; i++) {
        float w  = sh_w[i];
        uint2 u  = GT64[sh_idx[i] * (BATCH / 4) + t];
        float2 v0 = __half22float2(*reinterpret_cast<const __half2*>(&u.x));
        float2 v1 = __half22float2(*reinterpret_cast<const __half2*>(&u.y));
        acc.x += w * v0.x;
        acc.y += w * v0.y;
        acc.z += w * v1.x;
        acc.w += w * v1.y;
    }

    reinterpret_cast<float4*>(g_outT + (size_t)s * BATCH)[t] = acc;
}

// ---------------------------------------------------------------------------
// K5: transpose outT(2048 x 1024) -> out(1024 x 2048)
// blockDim (32,8), grid (BATCH/32, NSETS/32)
// ---------------------------------------------------------------------------
__global__ void k_out_transpose(float* __restrict__ out) {
    __shared__ float tile[32][33];
    int bx = blockIdx.x * 32;   // batch base (out col space of outT)
    int sy = blockIdx.y * 32;   // set base
    #pragma unroll
    for (int j = 0; j < 32; j += 8)
        tile[threadIdx.y + j][threadIdx.x] =
            g_outT[(size_t)(sy + threadIdx.y + j) * BATCH + bx + threadIdx.x];
    __syncthreads();
    #pragma unroll
    for (int j = 0; j < 32; j += 8)
        out[(size_t)(bx + threadIdx.y + j) * NSETS + sy + threadIdx.x] =
            tile[threadIdx.x][threadIdx.y + j];
}

// ---------------------------------------------------------------------------
// Launcher (graph-capturable: kernel launches only, default stream ordering)
// ---------------------------------------------------------------------------
extern "C" void kernel_launch(void* const* d_in, const int* in_sizes, int n_in,
                              void* d_out, int out_size) {
    const float* G      = (const float*)d_in[0];
    const float* logits = (const float*)d_in[1];
    const int*   fidx   = (const int*)d_in[2];
    const int*   seg    = (const int*)d_in[3];
    float*       out    = (float*)d_out;
    int total = in_sizes[1];

    k_offsets<<<(total + 255) / 256, 256>>>(seg, total);
    k_softmax<<<(NSETS * 32 + 255) / 256, 256>>>(logits);
    k_transpose<<<dim3(NGENE / 32, BATCH / 32), dim3(32, 8)>>>(G);
    k_agg<<<NSETS, 256>>>(fidx);
    k_out_transpose<<<dim3(BATCH / 32, NSETS / 32), dim3(32, 8)>>>(out);
}